// round 9
// baseline (speedup 1.0000x reference)
#include <cuda_runtime.h>
#include <cuda_bf16.h>
#include <math.h>
#include <stdint.h>

// Problem constants
#define BB 2048
#define KK 64
#define DIN 768
#define CF 64
#define MROWS (BB*KK)
#define SHARPNESS 1048576.0f
#define NCH 12            // K chunks of 64

// ---------------- scratch ----------------
__device__ float g_xfeat[BB*CF];
__device__ float g_scores[MROWS];
__device__ float g_sw[BB];
// Fragment-ordered bf16 hi+lo packed images of Wphi: [c][ks][nt][lane] uint4 {hx,hy,lx,ly}
__device__ __align__(16) uint4 g_Bfrag[NCH*4*8*32];   // 196KB, L2-resident

// ---------------- helpers ----------------
__device__ __forceinline__ void cpa16(void* smem, const void* g) {
    unsigned s = (unsigned)__cvta_generic_to_shared(smem);
    asm volatile("cp.async.cg.shared.global [%0], [%1], 16;" :: "r"(s), "l"(g));
}
#define CP_COMMIT() asm volatile("cp.async.commit_group;")
#define CP_WAIT1()  asm volatile("cp.async.wait_group 1;" ::: "memory")

__device__ __forceinline__ void cvt_split(float a0, float a1, uint32_t& hp, uint32_t& lp) {
    // pack {lo16=a0, hi16=a1} as bf16x2; lp = residuals
    asm("cvt.rn.satfinite.bf16x2.f32 %0, %1, %2;" : "=r"(hp) : "f"(a1), "f"(a0));
    float h0 = __uint_as_float(hp << 16);
    float h1 = __uint_as_float(hp & 0xffff0000u);
    float l0 = a0 - h0, l1 = a1 - h1;
    asm("cvt.rn.satfinite.bf16x2.f32 %0, %1, %2;" : "=r"(lp) : "f"(l1), "f"(l0));
}

__device__ __forceinline__ void mma_bf16(float* d, const uint32_t* a, uint32_t b0, uint32_t b1) {
    asm volatile("mma.sync.aligned.m16n8k16.row.col.f32.bf16.bf16.f32 "
        "{%0,%1,%2,%3}, {%4,%5,%6,%7}, {%8,%9}, {%0,%1,%2,%3};"
        : "+f"(d[0]), "+f"(d[1]), "+f"(d[2]), "+f"(d[3])
        : "r"(a[0]), "r"(a[1]), "r"(a[2]), "r"(a[3]), "r"(b0), "r"(b1));
}

// ---------------- kernel E: Wphi -> fragment-ordered packed bf16 hi/lo ----------------
__global__ void kernE(const float* __restrict__ Wphi) {
    int idx = blockIdx.x * 256 + threadIdx.x;    // < 12288
    int lane = idx & 31;
    int t = idx >> 5;                            // c*32 + ks*8 + nt
    int nt = t & 7, ks = (t >> 3) & 3, c = t >> 5;
    int g = lane >> 2, tig = lane & 3;
    int n = nt * 8 + g;
    int k0 = c * 64 + ks * 16 + 2 * tig;
    const float* wr = Wphi + n * DIN + k0;
    float w0 = wr[0], w1 = wr[1], w2 = wr[8], w3 = wr[9];
    uint32_t h01, l01, h23, l23;
    cvt_split(w0, w1, h01, l01);
    cvt_split(w2, w3, h23, l23);
    g_Bfrag[((c * 4 + ks) * 8 + nt) * 32 + lane] = make_uint4(h01, h23, l01, l23);
}

// ---------------- kernel A: x_feat = l2norm(x_im @ Wtheta^T + btheta) ----------------
__global__ void __launch_bounds__(256) kernA(const float* __restrict__ xim,
                                             const float* __restrict__ Wtheta,
                                             const float* __restrict__ btheta) {
    __shared__ __align__(16) float xs[8 * DIN];
    __shared__ float wred[8][2];
    int tid = threadIdx.x;
    int b0 = blockIdx.x * 8;
    const float4* src = (const float4*)(xim + (size_t)b0 * DIN);
    float4* d4 = (float4*)xs;
#pragma unroll
    for (int j = 0; j < 6; j++) d4[tid + 256 * j] = src[tid + 256 * j];
    __syncthreads();
    int f = tid & 63, g = tid >> 6;
    const float* wr = Wtheta + (size_t)f * DIN;
    const float* xa = xs + (2 * g) * DIN;
    const float* xb = xs + (2 * g + 1) * DIN;
    float a0 = 0.f, a1 = 0.f;
    for (int i = 0; i < DIN; i += 4) {
        float4 w4 = *(const float4*)(wr + i);
        float4 va = *(const float4*)(xa + i);
        float4 vb = *(const float4*)(xb + i);
        a0 += w4.x * va.x + w4.y * va.y + w4.z * va.z + w4.w * va.w;
        a1 += w4.x * vb.x + w4.y * vb.y + w4.z * vb.z + w4.w * vb.w;
    }
    a0 += btheta[f]; a1 += btheta[f];
    float s0 = a0 * a0, s1 = a1 * a1;
#pragma unroll
    for (int o = 1; o < 32; o <<= 1) {
        s0 += __shfl_xor_sync(0xffffffffu, s0, o);
        s1 += __shfl_xor_sync(0xffffffffu, s1, o);
    }
    int w = tid >> 5;
    if ((tid & 31) == 0) { wred[w][0] = s0; wred[w][1] = s1; }
    __syncthreads();
    int wb = g << 1;
    float n0 = wred[wb][0] + wred[wb + 1][0];
    float n1 = wred[wb][1] + wred[wb + 1][1];
    g_xfeat[(b0 + 2 * g) * CF + f]     = a0 / fmaxf(sqrtf(n0), 1e-12f);
    g_xfeat[(b0 + 2 * g + 1) * CF + f] = a1 / fmaxf(sqrtf(n1), 1e-12f);
}

// ---------------- kernel B: HMMA bf16 split-3 GEMM, A staged fp32 in smem ----------------
#define ASTR 68                 // fp32 row stride in smem (272B = 17x16B, 16B aligned)
#define S_A  0                  // 2 stages x 128*68*4 = 69632
#define S_B  69632              // 2 stages x 16KB = 32768
#define S_XF 102400             // 512
#define S_BP 102912             // 256
#define SMEMB_TOTAL 103168

__global__ void __launch_bounds__(256, 2) kernB(const float* __restrict__ pim,
                                                const float* __restrict__ bphi) {
    extern __shared__ __align__(16) char smem[];
    float* Asm = (float*)(smem + S_A);               // [2][128*ASTR]
    uint4* Bsm = (uint4*)(smem + S_B);               // [2][1024]
    float* xfsm = (float*)(smem + S_XF);
    float* bpsm = (float*)(smem + S_BP);

    int tid = threadIdx.x, w = tid >> 5, lane = tid & 31;
    int g = lane >> 2, tig = lane & 3;
    int m0 = blockIdx.x * 128;
    if (tid < 128) xfsm[tid] = g_xfeat[m0 + tid];
    else if (tid < 192) bpsm[tid - 128] = bphi[tid - 128];

    float acc[8][4];
#pragma unroll
    for (int nt = 0; nt < 8; nt++)
#pragma unroll
        for (int i = 0; i < 4; i++) acc[nt][i] = 0.f;

    // cp.async mapping: thread t covers rows (t>>4)+16i, cols 4*(t&15)..+3
    const int arow = (tid >> 4);
    const int acol = 4 * (tid & 15);
    const float* asrc = pim + (size_t)(m0 + arow) * DIN + acol;

    auto issue = [&](int c, int s) {
        float* Ad = Asm + s * (128 * ASTR);
#pragma unroll
        for (int i = 0; i < 8; i++)
            cpa16(Ad + (arow + 16 * i) * ASTR + acol, asrc + (size_t)16 * i * DIN + c * 64);
        const char* bs = (const char*)(g_Bfrag + (size_t)c * 1024) + tid * 64;
        char* bd = (char*)(Bsm + s * 1024) + tid * 64;
#pragma unroll
        for (int i = 0; i < 4; i++) cpa16(bd + 16 * i, bs + 16 * i);
        CP_COMMIT();
    };

    issue(0, 0); issue(1, 1);

    for (int c = 0; c < NCH; c++) {
        const int s = c & 1;
        CP_WAIT1();
        __syncthreads();
        const float* As = Asm + s * (128 * ASTR);
        const uint4* Bs = Bsm + s * 1024;
        const int r0 = 16 * w + g;
#pragma unroll
        for (int ks = 0; ks < 4; ks++) {
            const int kb = 16 * ks + 2 * tig;
            float2 f0 = *(const float2*)(As + r0 * ASTR + kb);
            float2 f1 = *(const float2*)(As + (r0 + 8) * ASTR + kb);
            float2 f2 = *(const float2*)(As + r0 * ASTR + kb + 8);
            float2 f3 = *(const float2*)(As + (r0 + 8) * ASTR + kb + 8);
            uint32_t Ah[4], Al[4];
            cvt_split(f0.x, f0.y, Ah[0], Al[0]);
            cvt_split(f1.x, f1.y, Ah[1], Al[1]);
            cvt_split(f2.x, f2.y, Ah[2], Al[2]);
            cvt_split(f3.x, f3.y, Ah[3], Al[3]);
#pragma unroll
            for (int nt = 0; nt < 8; nt++) {
                uint4 b = Bs[(ks * 8 + nt) * 32 + lane];
                mma_bf16(acc[nt], Ah, b.x, b.y);   // hi*hi
                mma_bf16(acc[nt], Al, b.x, b.y);   // lo*hi
                mma_bf16(acc[nt], Ah, b.z, b.w);   // hi*lo
            }
        }
        __syncthreads();
        if (c + 2 < NCH) issue(c + 2, s);
        else CP_COMMIT();
    }

    // Epilogue: u = D + bphi; score = dot(xf,u)/max(||u||,1e-12)
    int bi = w >> 2;
    float ps0 = 0.f, pd0 = 0.f, ps1 = 0.f, pd1 = 0.f;
#pragma unroll
    for (int nt = 0; nt < 8; nt++) {
        int col = nt * 8 + 2 * tig;
        float b0 = bpsm[col], b1 = bpsm[col + 1];
        float x0 = xfsm[bi * 64 + col], x1 = xfsm[bi * 64 + col + 1];
        float u;
        u = acc[nt][0] + b0; ps0 += u * u; pd0 += u * x0;
        u = acc[nt][1] + b1; ps0 += u * u; pd0 += u * x1;
        u = acc[nt][2] + b0; ps1 += u * u; pd1 += u * x0;
        u = acc[nt][3] + b1; ps1 += u * u; pd1 += u * x1;
    }
#pragma unroll
    for (int o = 1; o < 4; o <<= 1) {
        ps0 += __shfl_xor_sync(0xffffffffu, ps0, o);
        pd0 += __shfl_xor_sync(0xffffffffu, pd0, o);
        ps1 += __shfl_xor_sync(0xffffffffu, ps1, o);
        pd1 += __shfl_xor_sync(0xffffffffu, pd1, o);
    }
    if (tig == 0) {
        int r = m0 + 16 * w + g;
        g_scores[r]     = pd0 / fmaxf(sqrtf(ps0), 1e-12f);
        g_scores[r + 8] = pd1 / fmaxf(sqrtf(ps1), 1e-12f);
    }
}

// ---------------- kernel D: fused softmax + sparse weighted sum + Wg/Wo mix + blend ----------------
__global__ void __launch_bounds__(192) kernD(const float* __restrict__ x,
                                             const float* __restrict__ p,
                                             const float* __restrict__ Wg,
                                             const float* __restrict__ bgv,
                                             const float* __restrict__ Wo,
                                             const float* __restrict__ bov,
                                             const float* __restrict__ sig_scale,
                                             const float* __restrict__ sig_shift,
                                             float* __restrict__ out) {
    __shared__ __align__(16) float buf[DIN];    // float4-accessed: MUST be 16B aligned
    __shared__ __align__(16) float wsm[64];
    __shared__ float swsm;                       // scalar AFTER arrays
    int tid = threadIdx.x;
    int b = blockIdx.x;

    // warp 0: softmax over 64 scores + switch
    if (tid < 32) {
        int lane = tid;
        float s0 = g_scores[b * 64 + lane];
        float s1 = g_scores[b * 64 + 32 + lane];
        float t0 = s0 * SHARPNESS, t1 = s1 * SHARPNESS;
        float mraw = fmaxf(s0, s1), mt = fmaxf(t0, t1);
#pragma unroll
        for (int o = 16; o >= 1; o >>= 1) {
            mraw = fmaxf(mraw, __shfl_xor_sync(0xffffffffu, mraw, o));
            mt   = fmaxf(mt,   __shfl_xor_sync(0xffffffffu, mt, o));
        }
        float e0 = expf(t0 - mt), e1 = expf(t1 - mt);
        float sum = e0 + e1;
#pragma unroll
        for (int o = 16; o >= 1; o >>= 1) sum += __shfl_xor_sync(0xffffffffu, sum, o);
        float inv = 1.f / sum;
        wsm[lane]      = e0 * inv;
        wsm[lane + 32] = e1 * inv;
        if (lane == 0) {
            float z = mraw * sig_scale[0] + sig_shift[0];
            swsm = 1.f / (1.f + expf(-z));
        }
    }
    __syncthreads();

    float4 acc = make_float4(0.f, 0.f, 0.f, 0.f);
    const float4* pb = (const float4*)(p + (size_t)b * KK * DIN);
    for (int k = 0; k < 64; k++) {
        float w = wsm[k];
        if (w > 1e-10f) {
            float4 v = pb[k * 192 + tid];
            acc.x += w * v.x; acc.y += w * v.y; acc.z += w * v.z; acc.w += w * v.w;
        }
    }
    ((float4*)buf)[tid] = acc;
    __syncthreads();

    int o = tid / 64;
    int hw = (tid % 64) * 4;
    float gg0 = Wg[o * 3 + 0], gg1 = Wg[o * 3 + 1], gg2 = Wg[o * 3 + 2];
    float bgc = bgv[o];
    float t[4];
#pragma unroll
    for (int j = 0; j < 4; j++)
        t[j] = gg0 * buf[hw + j] + gg1 * buf[256 + hw + j] + gg2 * buf[512 + hw + j] + bgc;
    __syncthreads();
#pragma unroll
    for (int j = 0; j < 4; j++) buf[o * 256 + hw + j] = t[j];
    __syncthreads();

    float oo0 = Wo[o * 3 + 0], oo1 = Wo[o * 3 + 1], oo2 = Wo[o * 3 + 2];
    float boc = bov[o];
    float sw = swsm;
    float4 xv = ((const float4*)(x + (size_t)b * DIN))[tid];
    float pa0 = oo0 * buf[hw + 0] + oo1 * buf[256 + hw + 0] + oo2 * buf[512 + hw + 0] + boc;
    float pa1 = oo0 * buf[hw + 1] + oo1 * buf[256 + hw + 1] + oo2 * buf[512 + hw + 1] + boc;
    float pa2 = oo0 * buf[hw + 2] + oo1 * buf[256 + hw + 2] + oo2 * buf[512 + hw + 2] + boc;
    float pa3 = oo0 * buf[hw + 3] + oo1 * buf[256 + hw + 3] + oo2 * buf[512 + hw + 3] + boc;
    float4 ov;
    ov.x = xv.x * (1.f - sw) + pa0 * sw;
    ov.y = xv.y * (1.f - sw) + pa1 * sw;
    ov.z = xv.z * (1.f - sw) + pa2 * sw;
    ov.w = xv.w * (1.f - sw) + pa3 * sw;
    ((float4*)(out + (size_t)b * DIN))[tid] = ov;
}

// ---------------- launch ----------------
extern "C" void kernel_launch(void* const* d_in, const int* in_sizes, int n_in,
                              void* d_out, int out_size) {
    const float* x         = (const float*)d_in[0];
    const float* p         = (const float*)d_in[1];
    const float* x_im      = (const float*)d_in[2];
    const float* p_im      = (const float*)d_in[3];
    const float* Wtheta    = (const float*)d_in[4];
    const float* btheta    = (const float*)d_in[5];
    const float* Wphi      = (const float*)d_in[6];
    const float* bphi      = (const float*)d_in[7];
    const float* Wg        = (const float*)d_in[8];
    const float* bg        = (const float*)d_in[9];
    const float* Wo        = (const float*)d_in[10];
    const float* bo        = (const float*)d_in[11];
    const float* sig_scale = (const float*)d_in[12];
    const float* sig_shift = (const float*)d_in[13];
    float* out = (float*)d_out;

    cudaFuncSetAttribute(kernB, cudaFuncAttributeMaxDynamicSharedMemorySize, SMEMB_TOTAL);

    kernE<<<48, 256>>>(Wphi);
    kernA<<<BB / 8, 256>>>(x_im, Wtheta, btheta);
    kernB<<<MROWS / 128, 256, SMEMB_TOTAL>>>(p_im, bphi);
    kernD<<<BB, 192>>>(x, p, Wg, bg, Wo, bo, sig_scale, sig_shift, out);
}